// round 5
// baseline (speedup 1.0000x reference)
#include <cuda_runtime.h>
#include <cuda_bf16.h>
#include <math_constants.h>
#include <cstdint>

#define BB 2
#define SS 2048
#define HH 8
#define DK 512
#define TT (BB*SS)      // 4096 tokens
#define NH (BB*HH)      // 16 (b,h) pairs

// ---------------- static device scratch (no allocs allowed) ----------------
__device__ __nv_bfloat16 g_xh[TT*DK],  g_xl[TT*DK];
__device__ __nv_bfloat16 g_wqh[4096*512], g_wql[4096*512];
__device__ __nv_bfloat16 g_wkh[4096*512], g_wkl[4096*512];
__device__ __nv_bfloat16 g_wvh[4096*512], g_wvl[4096*512];
__device__ __nv_bfloat16 g_wuh[512*4096], g_wul[512*4096];
__device__ __nv_bfloat16 g_qh[NH*SS*DK], g_ql[NH*SS*DK];
__device__ __nv_bfloat16 g_kh[NH*SS*DK], g_kl[NH*SS*DK];
__device__ __nv_bfloat16 g_vh[NH*SS*DK], g_vl[NH*SS*DK];     // V natural [bh][t][e]
__device__ float         g_s [(size_t)NH*SS*SS];             // fp32 scores (lower tri only)
__device__ __nv_bfloat16 g_ph[(size_t)NH*SS*SS], g_pl[(size_t)NH*SS*SS];
__device__ __nv_bfloat16 g_hoh[(size_t)TT*4096], g_hol[(size_t)TT*4096];

// ---------------- helpers (baseline ISA: ldmatrix + mma.sync + cp.async) ---
__device__ __forceinline__ uint32_t smem_u32(const void* p){
    uint32_t a; asm("{ .reg .u64 t; cvta.to.shared.u64 t, %1; cvt.u32.u64 %0, t; }":"=r"(a):"l"(p)); return a;
}
__device__ __forceinline__ uint32_t swz(uint32_t off){ return off ^ ((off>>3)&0x70); }

__device__ __forceinline__ void ldsm4(uint32_t* r, uint32_t addr){
    asm volatile("ldmatrix.sync.aligned.m8n8.x4.shared.b16 {%0,%1,%2,%3}, [%4];"
        : "=r"(r[0]),"=r"(r[1]),"=r"(r[2]),"=r"(r[3]) : "r"(addr));
}
__device__ __forceinline__ void ldsm4t(uint32_t* r, uint32_t addr){
    asm volatile("ldmatrix.sync.aligned.m8n8.x4.trans.shared.b16 {%0,%1,%2,%3}, [%4];"
        : "=r"(r[0]),"=r"(r[1]),"=r"(r[2]),"=r"(r[3]) : "r"(addr));
}
__device__ __forceinline__ void mma16816(float* c, const uint32_t* a, uint32_t b0, uint32_t b1){
    asm volatile("mma.sync.aligned.m16n8k16.row.col.f32.bf16.bf16.f32 "
        "{%0,%1,%2,%3}, {%4,%5,%6,%7}, {%8,%9}, {%0,%1,%2,%3};"
        : "+f"(c[0]),"+f"(c[1]),"+f"(c[2]),"+f"(c[3])
        : "r"(a[0]),"r"(a[1]),"r"(a[2]),"r"(a[3]), "r"(b0),"r"(b1));
}
__device__ __forceinline__ void cp16(uint32_t dst, const void* src){
    asm volatile("cp.async.cg.shared.global [%0], [%1], 16;" :: "r"(dst), "l"(src) : "memory");
}
#define CP_COMMIT() asm volatile("cp.async.commit_group;" ::: "memory")
template<int N> __device__ __forceinline__ void cp_wait(){
    asm volatile("cp.async.wait_group %0;" :: "n"(N) : "memory");
}

#define STAGE 65536u        // 4 parts x 16KB per stage
#define NSTAGE 3
#define SMEM_DYN (STAGE*NSTAGE)   // 196608

// ---------------------------------------------------------------------------
// bf16x3 warp-MMA GEMM, 3-stage cp.async pipeline.
// D[128,128] tile of scale*(A[M,K] . op(B)); D = Ah*Bh + Ah*Bl + Al*Bh.
// BT=true : B[N,K] row-major (NT).  BT=false: B[K,N] row-major (NN, trans-ldsm).
// Block 256 thr = 8 warps (4 M x 2 N), warp tile 32x64, BK=64.
// EPI: 0 fp32 + scale + causal mask | 1 fp32 plain | 2 split-bf16 row-major
// ---------------------------------------------------------------------------
template<int EPI, bool BT>
__device__ void gemm_mma(
    const __nv_bfloat16* __restrict__ Ah, const __nv_bfloat16* __restrict__ Al, int lda,
    const __nv_bfloat16* __restrict__ Bh, const __nv_bfloat16* __restrict__ Bl, int ldb,
    int kCount, int m0, int n0, float scale,
    float* __restrict__ Cf, int ldc,
    __nv_bfloat16* __restrict__ Oh, __nv_bfloat16* __restrict__ Ol, int orow)
{
    extern __shared__ char sm[];
    const int tid = threadIdx.x, lane = tid & 31, wid = tid >> 5;
    const int wm = wid & 3, wn = wid >> 2;
    const int g = lane >> 2, t4 = lane & 3;
    const uint32_t sbase = smem_u32(sm);

    const int mtx = lane >> 3, ri = lane & 7;
    const int lrow = ((mtx & 1) << 3) + ri;   // A: row within 16-row group
    const int lkh  = mtx >> 1;                // A: k-half chunk
    // NN B trans-ldsm coords
    const int brow = ((lane >> 4) << 3) + ri; // row within k16 group
    const int bchh = (lane >> 3) & 1;         // n8 half

    const __nv_bfloat16* Ap[2] = {Ah, Al};
    const __nv_bfloat16* Bp[2] = {Bh, Bl};

    float acc[64];
#pragma unroll
    for (int i = 0; i < 64; i++) acc[i] = 0.f;

    const int nk = kCount >> 6;

    // ---- chunk loader ----
    auto load_chunk = [&](int kc) {
        const uint32_t sb = sbase + (uint32_t)(kc % NSTAGE) * STAGE;
        const int k0 = kc << 6;
#pragma unroll
        for (int p = 0; p < 2; p++)
#pragma unroll
            for (int i = 0; i < 4; i++) {
                int lin = tid + i * 256;
                int r = lin >> 3, ch = lin & 7;
                cp16(sb + p * 16384 + swz(r * 128 + ch * 16),
                     Ap[p] + (size_t)(m0 + r) * lda + k0 + ch * 8);
            }
        if (BT) {
#pragma unroll
            for (int p = 0; p < 2; p++)
#pragma unroll
                for (int i = 0; i < 4; i++) {
                    int lin = tid + i * 256;
                    int r = lin >> 3, ch = lin & 7;
                    cp16(sb + 32768 + p * 16384 + swz(r * 128 + ch * 16),
                         Bp[p] + (size_t)(n0 + r) * ldb + k0 + ch * 8);
                }
        } else {
#pragma unroll
            for (int p = 0; p < 2; p++)
#pragma unroll
                for (int i = 0; i < 4; i++) {
                    int lin = tid + i * 256;
                    int r = lin >> 4, ch = lin & 15;
                    cp16(sb + 32768 + p * 16384 + (uint32_t)(r * 256 + ((ch ^ (r & 7)) * 16)),
                         Bp[p] + (size_t)(k0 + r) * ldb + n0 + ch * 8);
                }
        }
    };

    load_chunk(0);            CP_COMMIT();
    if (nk > 1) load_chunk(1);
    CP_COMMIT();

    for (int kc = 0; kc < nk; kc++) {
        if (kc + 2 < nk) load_chunk(kc + 2);
        CP_COMMIT();
        cp_wait<2>();
        __syncthreads();

        const uint32_t cb = sbase + (uint32_t)(kc % NSTAGE) * STAGE;
#pragma unroll
        for (int kk = 0; kk < 4; kk++) {
            uint32_t aH[8], aL[8];
            {
                const int chb = (kk * 2 + lkh) * 16;
#pragma unroll
                for (int s = 0; s < 2; s++) {
                    uint32_t off = swz((uint32_t)(wm * 32 + s * 16 + lrow) * 128 + chb);
                    ldsm4(aH + s * 4, cb + off);
                    ldsm4(aL + s * 4, cb + 16384 + off);
                }
            }
#pragma unroll
            for (int nb = 0; nb < 4; nb++) {
                uint32_t bh[4], bl[4];
                if (BT) {
                    const int chb = (kk * 2 + lkh) * 16;
                    uint32_t off = swz((uint32_t)(wn * 64 + nb * 16 + lrow) * 128 + chb);
                    ldsm4(bh, cb + 32768 + off);
                    ldsm4(bl, cb + 49152 + off);
                } else {
                    int r  = kk * 16 + brow;
                    int ch = (wn * 64 + nb * 16) / 8 + bchh;
                    uint32_t off = (uint32_t)(r * 256 + ((ch ^ (r & 7)) * 16));
                    ldsm4t(bh, cb + 32768 + off);
                    ldsm4t(bl, cb + 49152 + off);
                }
#pragma unroll
                for (int mi = 0; mi < 2; mi++) {
#pragma unroll
                    for (int sub = 0; sub < 2; sub++) {
                        float* c = acc + (mi * 8 + nb * 2 + sub) * 4;
                        mma16816(c, aH + mi * 4, bh[sub], bh[sub + 2]);
                        mma16816(c, aH + mi * 4, bl[sub], bl[sub + 2]);
                        mma16816(c, aL + mi * 4, bh[sub], bh[sub + 2]);
                    }
                }
            }
        }
        __syncthreads();
    }

    // ---- epilogue straight from registers
#pragma unroll
    for (int mi = 0; mi < 2; mi++) {
#pragma unroll
        for (int nbi = 0; nbi < 8; nbi++) {
            const float* c = acc + (mi * 8 + nbi) * 4;
            int rl = wm * 32 + mi * 16 + g;       // local row (and rl+8)
            int cl = wn * 64 + nbi * 8 + 2 * t4;  // local col (even)
            if (EPI <= 1) {
                int gr0 = m0 + rl, gc = n0 + cl;
                float v0 = c[0] * scale, v1 = c[1] * scale;
                float v2 = c[2] * scale, v3 = c[3] * scale;
                if (EPI == 0) {
                    if (gc     > gr0)     v0 = -CUDART_INF_F;
                    if (gc + 1 > gr0)     v1 = -CUDART_INF_F;
                    if (gc     > gr0 + 8) v2 = -CUDART_INF_F;
                    if (gc + 1 > gr0 + 8) v3 = -CUDART_INF_F;
                }
                *reinterpret_cast<float2*>(Cf + (size_t)gr0 * ldc + gc)       = make_float2(v0, v1);
                *reinterpret_cast<float2*>(Cf + (size_t)(gr0 + 8) * ldc + gc) = make_float2(v2, v3);
            } else {
                __nv_bfloat16 h0 = __float2bfloat16(c[0]);
                __nv_bfloat16 h1 = __float2bfloat16(c[1]);
                __nv_bfloat16 h2 = __float2bfloat16(c[2]);
                __nv_bfloat16 h3 = __float2bfloat16(c[3]);
                __nv_bfloat16 l0 = __float2bfloat16(c[0] - __bfloat162float(h0));
                __nv_bfloat16 l1 = __float2bfloat16(c[1] - __bfloat162float(h1));
                __nv_bfloat16 l2 = __float2bfloat16(c[2] - __bfloat162float(h2));
                __nv_bfloat16 l3 = __float2bfloat16(c[3] - __bfloat162float(h3));
                size_t gm = (size_t)(m0 + rl);
                size_t o0 = gm * orow + cl, o1 = o0 + (size_t)8 * orow;
                *reinterpret_cast<__nv_bfloat162*>(Oh + o0) = __nv_bfloat162(h0, h1);
                *reinterpret_cast<__nv_bfloat162*>(Ol + o0) = __nv_bfloat162(l0, l1);
                *reinterpret_cast<__nv_bfloat162*>(Oh + o1) = __nv_bfloat162(h2, h3);
                *reinterpret_cast<__nv_bfloat162*>(Ol + o1) = __nv_bfloat162(l2, l3);
            }
        }
    }
}

// ---------------------------------------------------------------------------
// All 5 input splits in one launch: z = {x, Wq, Wk, Wv, Wu}
__global__ void __launch_bounds__(256) k_split_all(
    const float* __restrict__ x,  const float* __restrict__ Wq,
    const float* __restrict__ Wk, const float* __restrict__ Wv,
    const float* __restrict__ Wu)
{
    const int z = blockIdx.y;
    const float* s;
    __nv_bfloat16 *h, *l;
    switch (z) {
        case 0: s = x;  h = g_xh;  l = g_xl;  break;
        case 1: s = Wq; h = g_wqh; l = g_wql; break;
        case 2: s = Wk; h = g_wkh; l = g_wkl; break;
        case 3: s = Wv; h = g_wvh; l = g_wvl; break;
        default: s = Wu; h = g_wuh; l = g_wul; break;
    }
    int i = blockIdx.x * blockDim.x + threadIdx.x;
    float4 v = reinterpret_cast<const float4*>(s)[i];
    __nv_bfloat16 h0=__float2bfloat16(v.x), h1=__float2bfloat16(v.y),
                  h2=__float2bfloat16(v.z), h3=__float2bfloat16(v.w);
    __nv_bfloat16 l0=__float2bfloat16(v.x-__bfloat162float(h0)),
                  l1=__float2bfloat16(v.y-__bfloat162float(h1)),
                  l2=__float2bfloat16(v.z-__bfloat162float(h2)),
                  l3=__float2bfloat16(v.w-__bfloat162float(h3));
    uint2 hv = make_uint2((uint32_t)__bfloat16_as_ushort(h0)|((uint32_t)__bfloat16_as_ushort(h1)<<16),
                          (uint32_t)__bfloat16_as_ushort(h2)|((uint32_t)__bfloat16_as_ushort(h3)<<16));
    uint2 lv = make_uint2((uint32_t)__bfloat16_as_ushort(l0)|((uint32_t)__bfloat16_as_ushort(l1)<<16),
                          (uint32_t)__bfloat16_as_ushort(l2)|((uint32_t)__bfloat16_as_ushort(l3)<<16));
    reinterpret_cast<uint2*>(h)[i] = hv;
    reinterpret_cast<uint2*>(l)[i] = lv;
}

__global__ void __launch_bounds__(256) k_qkv_mma(void)
{
    int n0 = blockIdx.x * 128, m0 = blockIdx.y * 128, z = blockIdx.z;
    int b = m0 >> 11, h = n0 >> 9, e0 = n0 & 511;
    const __nv_bfloat16 *Wh, *Wl;
    __nv_bfloat16 *OH, *OL;
    if (z == 0)      { Wh = g_wqh; Wl = g_wql; OH = g_qh; OL = g_ql; }
    else if (z == 1) { Wh = g_wkh; Wl = g_wkl; OH = g_kh; OL = g_kl; }
    else             { Wh = g_wvh; Wl = g_wvl; OH = g_vh; OL = g_vl; }
    // dest layout [bh][s][512]: base = (b*HH + h)*SS*DK + e0, minus m-row offset fold
    size_t base = ((size_t)(b * HH + h) * SS) * DK + e0 - (size_t)(b * SS) * DK;
    gemm_mma<2, true>(g_xh, g_xl, 512, Wh, Wl, 512, 512, m0, n0, 1.f,
                      nullptr, 0, OH + base, OL + base, 512);
}

__global__ void __launch_bounds__(256) k_scores_mma(void)
{
    int bh = blockIdx.z, n0 = blockIdx.x * 128, m0 = blockIdx.y * 128;
    if (n0 > m0) return;   // fully masked tile: never written, never read
    float* Cf = g_s + (size_t)bh * SS * SS;
    size_t ob = (size_t)bh * SS * DK;
    gemm_mma<0, true>(g_qh + ob, g_ql + ob, 512, g_kh + ob, g_kl + ob, 512,
                      512, m0, n0, 0.04419417382415922f, Cf, SS, nullptr, nullptr, 0);
}

// Softmax over valid (causal) prefix only.
__global__ void __launch_bounds__(256) k_softmax(void)
{
    int row  = blockIdx.x * 8 + (threadIdx.x >> 5);
    int lane = threadIdx.x & 31;
    int r    = row & (SS - 1);
    int rt   = r >> 7;             // last valid 128-col block
    const float4* p = reinterpret_cast<const float4*>(g_s + (size_t)row * SS);
    uint2* ph = reinterpret_cast<uint2*>(g_ph + (size_t)row * SS);
    uint2* pl = reinterpret_cast<uint2*>(g_pl + (size_t)row * SS);

    float4 v[16];
    float mx = -CUDART_INF_F;
#pragma unroll
    for (int i = 0; i < 16; i++) {
        if (i <= rt) {
            v[i] = p[lane + i * 32];
            mx = fmaxf(mx, fmaxf(fmaxf(v[i].x, v[i].y), fmaxf(v[i].z, v[i].w)));
        }
    }
#pragma unroll
    for (int o = 16; o; o >>= 1) mx = fmaxf(mx, __shfl_xor_sync(0xffffffffu, mx, o));
    float sum = 0.0f;
#pragma unroll
    for (int i = 0; i < 16; i++) {
        if (i > rt) continue;
        v[i].x = __expf(v[i].x - mx); v[i].y = __expf(v[i].y - mx);
        v[i].z = __expf(v[i].z - mx); v[i].w = __expf(v[i].w - mx);
        sum += (v[i].x + v[i].y) + (v[i].z + v[i].w);
    }
#pragma unroll
    for (int o = 16; o; o >>= 1) sum += __shfl_xor_sync(0xffffffffu, sum, o);
    float inv = 1.0f / sum;
#pragma unroll
    for (int i = 0; i < 16; i++) {
        if (i > rt) continue;
        float a0 = v[i].x*inv, a1 = v[i].y*inv, a2 = v[i].z*inv, a3 = v[i].w*inv;
        __nv_bfloat16 h0=__float2bfloat16(a0), h1=__float2bfloat16(a1),
                      h2=__float2bfloat16(a2), h3=__float2bfloat16(a3);
        __nv_bfloat16 l0=__float2bfloat16(a0-__bfloat162float(h0)),
                      l1=__float2bfloat16(a1-__bfloat162float(h1)),
                      l2=__float2bfloat16(a2-__bfloat162float(h2)),
                      l3=__float2bfloat16(a3-__bfloat162float(h3));
        ph[lane + i*32] = make_uint2(
            (uint32_t)__bfloat16_as_ushort(h0)|((uint32_t)__bfloat16_as_ushort(h1)<<16),
            (uint32_t)__bfloat16_as_ushort(h2)|((uint32_t)__bfloat16_as_ushort(h3)<<16));
        pl[lane + i*32] = make_uint2(
            (uint32_t)__bfloat16_as_ushort(l0)|((uint32_t)__bfloat16_as_ushort(l1)<<16),
            (uint32_t)__bfloat16_as_ushort(l2)|((uint32_t)__bfloat16_as_ushort(l3)<<16));
    }
}

// PV: NN gemm — A = probs [s][t], B = V natural [t][dk]
__global__ void __launch_bounds__(256) k_pv_mma(void)
{
    int bh = blockIdx.z, b = bh >> 3, h = bh & 7;
    int m0 = blockIdx.y * 128, n0 = blockIdx.x * 128;
    const __nv_bfloat16* Ah = g_ph + (size_t)bh * SS * SS;
    const __nv_bfloat16* Al = g_pl + (size_t)bh * SS * SS;
    const __nv_bfloat16* Bh = g_vh + (size_t)bh * SS * DK;
    const __nv_bfloat16* Bl = g_vl + (size_t)bh * SS * DK;
    size_t base = (size_t)b * SS * 4096 + h * 512 + n0;
    gemm_mma<2, false>(Ah, Al, SS, Bh, Bl, 512, m0 + 128, m0, n0, 1.f,
                       nullptr, 0, g_hoh + base, g_hol + base, 4096);
}

__global__ void __launch_bounds__(256) k_out_mma(float* __restrict__ out)
{
    int m0 = blockIdx.y * 128, n0 = blockIdx.x * 128;
    gemm_mma<1, true>(g_hoh, g_hol, 4096, g_wuh, g_wul, 4096, 4096, m0, n0, 1.f,
                      out, 512, nullptr, nullptr, 0);
}

// ---------------------------------------------------------------------------
extern "C" void kernel_launch(void* const* d_in, const int* in_sizes, int n_in,
                              void* d_out, int out_size)
{
    const float* x  = (const float*)d_in[0];
    const float* Wq = (const float*)d_in[1];
    const float* Wk = (const float*)d_in[2];
    const float* Wv = (const float*)d_in[3];
    const float* Wu = (const float*)d_in[4];
    float* out = (float*)d_out;

    cudaFuncSetAttribute(k_qkv_mma,    cudaFuncAttributeMaxDynamicSharedMemorySize, SMEM_DYN);
    cudaFuncSetAttribute(k_scores_mma, cudaFuncAttributeMaxDynamicSharedMemorySize, SMEM_DYN);
    cudaFuncSetAttribute(k_pv_mma,     cudaFuncAttributeMaxDynamicSharedMemorySize, SMEM_DYN);
    cudaFuncSetAttribute(k_out_mma,    cudaFuncAttributeMaxDynamicSharedMemorySize, SMEM_DYN);

    const int n4 = TT * DK / 4;           // 524288 float4s per 4096x512 array
    k_split_all <<<dim3(n4 / 256, 5), 256>>>(x, Wq, Wk, Wv, Wu);

    k_qkv_mma   <<<dim3(32, 32, 3),  256, SMEM_DYN>>>();
    k_scores_mma<<<dim3(16, 16, NH), 256, SMEM_DYN>>>();
    k_softmax   <<<NH * SS / 8, 256>>>();
    k_pv_mma    <<<dim3(4, 16, NH),  256, SMEM_DYN>>>();
    k_out_mma   <<<dim3(4, 32, 1),   256, SMEM_DYN>>>(out);
}

// round 6
// speedup vs baseline: 1.0216x; 1.0216x over previous
#include <cuda_runtime.h>
#include <cuda_bf16.h>
#include <math_constants.h>
#include <cstdint>

#define BB 2
#define SS 2048
#define HH 8
#define DK 512
#define TT (BB*SS)      // 4096 tokens
#define NH (BB*HH)      // 16 (b,h) pairs

// ---------------- static device scratch (no allocs allowed) ----------------
__device__ __nv_bfloat16 g_xh[TT*DK],  g_xl[TT*DK];
__device__ __nv_bfloat16 g_wqh[4096*512], g_wql[4096*512];
__device__ __nv_bfloat16 g_wkh[4096*512], g_wkl[4096*512];
__device__ __nv_bfloat16 g_wvh[4096*512], g_wvl[4096*512];
__device__ __nv_bfloat16 g_wuh[512*4096], g_wul[512*4096];
__device__ __nv_bfloat16 g_qh[NH*SS*DK], g_ql[NH*SS*DK];
__device__ __nv_bfloat16 g_kh[NH*SS*DK], g_kl[NH*SS*DK];
__device__ __nv_bfloat16 g_vh[NH*SS*DK], g_vl[NH*SS*DK];     // V natural [bh][t][e]
__device__ float         g_s [(size_t)NH*SS*SS];             // fp32 scores (lower tri only)
__device__ __nv_bfloat16 g_ph[(size_t)NH*SS*SS], g_pl[(size_t)NH*SS*SS];
__device__ __nv_bfloat16 g_hoh[(size_t)TT*4096], g_hol[(size_t)TT*4096];

// ---------------- helpers (baseline ISA: ldmatrix + mma.sync + cp.async) ---
__device__ __forceinline__ uint32_t smem_u32(const void* p){
    uint32_t a; asm("{ .reg .u64 t; cvta.to.shared.u64 t, %1; cvt.u32.u64 %0, t; }":"=r"(a):"l"(p)); return a;
}
__device__ __forceinline__ void ldsm4(uint32_t* r, uint32_t addr){
    asm volatile("ldmatrix.sync.aligned.m8n8.x4.shared.b16 {%0,%1,%2,%3}, [%4];"
        : "=r"(r[0]),"=r"(r[1]),"=r"(r[2]),"=r"(r[3]) : "r"(addr));
}
__device__ __forceinline__ void ldsm4t(uint32_t* r, uint32_t addr){
    asm volatile("ldmatrix.sync.aligned.m8n8.x4.trans.shared.b16 {%0,%1,%2,%3}, [%4];"
        : "=r"(r[0]),"=r"(r[1]),"=r"(r[2]),"=r"(r[3]) : "r"(addr));
}
__device__ __forceinline__ void mma16816(float* c, const uint32_t* a, uint32_t b0, uint32_t b1){
    asm volatile("mma.sync.aligned.m16n8k16.row.col.f32.bf16.bf16.f32 "
        "{%0,%1,%2,%3}, {%4,%5,%6,%7}, {%8,%9}, {%0,%1,%2,%3};"
        : "+f"(c[0]),"+f"(c[1]),"+f"(c[2]),"+f"(c[3])
        : "r"(a[0]),"r"(a[1]),"r"(a[2]),"r"(a[3]), "r"(b0),"r"(b1));
}
__device__ __forceinline__ void cp16(uint32_t dst, const void* src){
    asm volatile("cp.async.cg.shared.global [%0], [%1], 16;" :: "r"(dst), "l"(src) : "memory");
}
#define CP_COMMIT() asm volatile("cp.async.commit_group;" ::: "memory")
template<int N> __device__ __forceinline__ void cp_wait(){
    asm volatile("cp.async.wait_group %0;" :: "n"(N) : "memory");
}

// swizzles: A / B-NT tiles have 64B rows (BK=32); B-NN tiles have 256B rows.
__device__ __forceinline__ uint32_t swzA(uint32_t row, uint32_t ch){
    return row * 64 + ((ch ^ ((row >> 1) & 3)) << 4);
}
__device__ __forceinline__ uint32_t swzB(uint32_t row, uint32_t ch){
    return row * 256 + ((ch ^ (row & 7)) << 4);
}

#define STAGE 32768u        // 4 parts x 8KB per stage (BK=32)
#define NSTAGE 3
#define SMEM_DYN (STAGE*NSTAGE)   // 98304 -> 2 CTAs/SM

// ---------------------------------------------------------------------------
// bf16x3 warp-MMA GEMM, 3-stage cp.async pipeline, BK=32, 2 CTAs/SM.
// D[128,128] tile of scale*(A[M,K] . op(B)); D = Ah*Bh + Ah*Bl + Al*Bh.
// BT=true : B[N,K] row-major (NT).  BT=false: B[K,N] row-major (NN, trans-ldsm).
// Block 256 thr = 8 warps (4 M x 2 N), warp tile 32x64.
// EPI: 0 fp32 + scale + causal mask | 1 fp32 plain | 2 split-bf16 row-major
// ---------------------------------------------------------------------------
template<int EPI, bool BT>
__device__ void gemm_mma(
    const __nv_bfloat16* __restrict__ Ah, const __nv_bfloat16* __restrict__ Al, int lda,
    const __nv_bfloat16* __restrict__ Bh, const __nv_bfloat16* __restrict__ Bl, int ldb,
    int kCount, int m0, int n0, float scale,
    float* __restrict__ Cf, int ldc,
    __nv_bfloat16* __restrict__ Oh, __nv_bfloat16* __restrict__ Ol, int orow)
{
    extern __shared__ char sm[];
    const int tid = threadIdx.x, lane = tid & 31, wid = tid >> 5;
    const int wm = wid & 3, wn = wid >> 2;
    const int g = lane >> 2, t4 = lane & 3;
    const uint32_t sbase = smem_u32(sm);

    const int mtx = lane >> 3, ri = lane & 7;
    const int lrow = ((mtx & 1) << 3) + ri;   // A: row within 16-row group
    const int lkh  = mtx >> 1;                // A: 16B half within k16
    // NN B trans-ldsm coords
    const int brow = ((lane >> 4) << 3) + ri; // row within k16 group
    const int bchh = (lane >> 3) & 1;         // n8 half

    const __nv_bfloat16* Ap[2] = {Ah, Al};
    const __nv_bfloat16* Bp[2] = {Bh, Bl};

    float acc[64];
#pragma unroll
    for (int i = 0; i < 64; i++) acc[i] = 0.f;

    const int nk = kCount >> 5;

    // ---- chunk loader (BK=32) ----
    auto load_chunk = [&](int kc) {
        const uint32_t sb = sbase + (uint32_t)(kc % NSTAGE) * STAGE;
        const int k0 = kc << 5;
        // A h/l: 128 rows x 64B, 2 cp16/thread/part
#pragma unroll
        for (int p = 0; p < 2; p++)
#pragma unroll
            for (int i = 0; i < 2; i++) {
                int lin = tid + i * 256;
                int r = lin >> 2, ch = lin & 3;
                cp16(sb + p * 8192 + swzA(r, ch),
                     Ap[p] + (size_t)(m0 + r) * lda + k0 + ch * 8);
            }
        if (BT) {
#pragma unroll
            for (int p = 0; p < 2; p++)
#pragma unroll
                for (int i = 0; i < 2; i++) {
                    int lin = tid + i * 256;
                    int r = lin >> 2, ch = lin & 3;
                    cp16(sb + 16384 + p * 8192 + swzA(r, ch),
                         Bp[p] + (size_t)(n0 + r) * ldb + k0 + ch * 8);
                }
        } else {
            // B[K,N]: 32 rows x 256B
#pragma unroll
            for (int p = 0; p < 2; p++)
#pragma unroll
                for (int i = 0; i < 2; i++) {
                    int lin = tid + i * 256;
                    int r = lin >> 4, ch = lin & 15;
                    cp16(sb + 16384 + p * 8192 + swzB(r, ch),
                         Bp[p] + (size_t)(k0 + r) * ldb + n0 + ch * 8);
                }
        }
    };

    load_chunk(0);            CP_COMMIT();
    if (nk > 1) load_chunk(1);
    CP_COMMIT();

    for (int kc = 0; kc < nk; kc++) {
        if (kc + 2 < nk) load_chunk(kc + 2);
        CP_COMMIT();
        cp_wait<2>();
        __syncthreads();

        const uint32_t cb = sbase + (uint32_t)(kc % NSTAGE) * STAGE;
#pragma unroll
        for (int kk = 0; kk < 2; kk++) {
            const int ch = kk * 2 + lkh;
            uint32_t aH[8], aL[8];
#pragma unroll
            for (int s = 0; s < 2; s++) {
                uint32_t off = swzA((uint32_t)(wm * 32 + s * 16 + lrow), ch);
                ldsm4(aH + s * 4, cb + off);
                ldsm4(aL + s * 4, cb + 8192 + off);
            }
#pragma unroll
            for (int nb = 0; nb < 4; nb++) {
                uint32_t bh[4], bl[4];
                if (BT) {
                    uint32_t off = swzA((uint32_t)(wn * 64 + nb * 16 + lrow), ch);
                    ldsm4(bh, cb + 16384 + off);
                    ldsm4(bl, cb + 24576 + off);
                } else {
                    uint32_t off = swzB((uint32_t)(kk * 16 + brow),
                                        (uint32_t)(wn * 8 + nb * 2 + bchh));
                    ldsm4t(bh, cb + 16384 + off);
                    ldsm4t(bl, cb + 24576 + off);
                }
#pragma unroll
                for (int mi = 0; mi < 2; mi++) {
#pragma unroll
                    for (int sub = 0; sub < 2; sub++) {
                        float* c = acc + (mi * 8 + nb * 2 + sub) * 4;
                        mma16816(c, aH + mi * 4, bh[sub], bh[sub + 2]);
                        mma16816(c, aH + mi * 4, bl[sub], bl[sub + 2]);
                        mma16816(c, aL + mi * 4, bh[sub], bh[sub + 2]);
                    }
                }
            }
        }
        __syncthreads();
    }

    // ---- epilogue straight from registers
#pragma unroll
    for (int mi = 0; mi < 2; mi++) {
#pragma unroll
        for (int nbi = 0; nbi < 8; nbi++) {
            const float* c = acc + (mi * 8 + nbi) * 4;
            int rl = wm * 32 + mi * 16 + g;       // local row (and rl+8)
            int cl = wn * 64 + nbi * 8 + 2 * t4;  // local col (even)
            if (EPI <= 1) {
                int gr0 = m0 + rl, gc = n0 + cl;
                float v0 = c[0] * scale, v1 = c[1] * scale;
                float v2 = c[2] * scale, v3 = c[3] * scale;
                if (EPI == 0) {
                    if (gc     > gr0)     v0 = -CUDART_INF_F;
                    if (gc + 1 > gr0)     v1 = -CUDART_INF_F;
                    if (gc     > gr0 + 8) v2 = -CUDART_INF_F;
                    if (gc + 1 > gr0 + 8) v3 = -CUDART_INF_F;
                }
                *reinterpret_cast<float2*>(Cf + (size_t)gr0 * ldc + gc)       = make_float2(v0, v1);
                *reinterpret_cast<float2*>(Cf + (size_t)(gr0 + 8) * ldc + gc) = make_float2(v2, v3);
            } else {
                __nv_bfloat16 h0 = __float2bfloat16(c[0]);
                __nv_bfloat16 h1 = __float2bfloat16(c[1]);
                __nv_bfloat16 h2 = __float2bfloat16(c[2]);
                __nv_bfloat16 h3 = __float2bfloat16(c[3]);
                __nv_bfloat16 l0 = __float2bfloat16(c[0] - __bfloat162float(h0));
                __nv_bfloat16 l1 = __float2bfloat16(c[1] - __bfloat162float(h1));
                __nv_bfloat16 l2 = __float2bfloat16(c[2] - __bfloat162float(h2));
                __nv_bfloat16 l3 = __float2bfloat16(c[3] - __bfloat162float(h3));
                size_t gm = (size_t)(m0 + rl);
                size_t o0 = gm * orow + cl, o1 = o0 + (size_t)8 * orow;
                *reinterpret_cast<__nv_bfloat162*>(Oh + o0) = __nv_bfloat162(h0, h1);
                *reinterpret_cast<__nv_bfloat162*>(Ol + o0) = __nv_bfloat162(l0, l1);
                *reinterpret_cast<__nv_bfloat162*>(Oh + o1) = __nv_bfloat162(h2, h3);
                *reinterpret_cast<__nv_bfloat162*>(Ol + o1) = __nv_bfloat162(l2, l3);
            }
        }
    }
}

// ---------------------------------------------------------------------------
// All 5 input splits in one launch: z = {x, Wq, Wk, Wv, Wu}
__global__ void __launch_bounds__(256) k_split_all(
    const float* __restrict__ x,  const float* __restrict__ Wq,
    const float* __restrict__ Wk, const float* __restrict__ Wv,
    const float* __restrict__ Wu)
{
    const int z = blockIdx.y;
    const float* s;
    __nv_bfloat16 *h, *l;
    switch (z) {
        case 0: s = x;  h = g_xh;  l = g_xl;  break;
        case 1: s = Wq; h = g_wqh; l = g_wql; break;
        case 2: s = Wk; h = g_wkh; l = g_wkl; break;
        case 3: s = Wv; h = g_wvh; l = g_wvl; break;
        default: s = Wu; h = g_wuh; l = g_wul; break;
    }
    int i = blockIdx.x * blockDim.x + threadIdx.x;
    float4 v = reinterpret_cast<const float4*>(s)[i];
    __nv_bfloat16 h0=__float2bfloat16(v.x), h1=__float2bfloat16(v.y),
                  h2=__float2bfloat16(v.z), h3=__float2bfloat16(v.w);
    __nv_bfloat16 l0=__float2bfloat16(v.x-__bfloat162float(h0)),
                  l1=__float2bfloat16(v.y-__bfloat162float(h1)),
                  l2=__float2bfloat16(v.z-__bfloat162float(h2)),
                  l3=__float2bfloat16(v.w-__bfloat162float(h3));
    uint2 hv = make_uint2((uint32_t)__bfloat16_as_ushort(h0)|((uint32_t)__bfloat16_as_ushort(h1)<<16),
                          (uint32_t)__bfloat16_as_ushort(h2)|((uint32_t)__bfloat16_as_ushort(h3)<<16));
    uint2 lv = make_uint2((uint32_t)__bfloat16_as_ushort(l0)|((uint32_t)__bfloat16_as_ushort(l1)<<16),
                          (uint32_t)__bfloat16_as_ushort(l2)|((uint32_t)__bfloat16_as_ushort(l3)<<16));
    reinterpret_cast<uint2*>(h)[i] = hv;
    reinterpret_cast<uint2*>(l)[i] = lv;
}

__global__ void __launch_bounds__(256, 2) k_qkv_mma(void)
{
    int n0 = blockIdx.x * 128, m0 = blockIdx.y * 128, z = blockIdx.z;
    int b = m0 >> 11, h = n0 >> 9, e0 = n0 & 511;
    const __nv_bfloat16 *Wh, *Wl;
    __nv_bfloat16 *OH, *OL;
    if (z == 0)      { Wh = g_wqh; Wl = g_wql; OH = g_qh; OL = g_ql; }
    else if (z == 1) { Wh = g_wkh; Wl = g_wkl; OH = g_kh; OL = g_kl; }
    else             { Wh = g_wvh; Wl = g_wvl; OH = g_vh; OL = g_vl; }
    size_t base = ((size_t)(b * HH + h) * SS) * DK + e0 - (size_t)(b * SS) * DK;
    gemm_mma<2, true>(g_xh, g_xl, 512, Wh, Wl, 512, 512, m0, n0, 1.f,
                      nullptr, 0, OH + base, OL + base, 512);
}

__global__ void __launch_bounds__(256, 2) k_scores_mma(void)
{
    int bh = blockIdx.z, n0 = blockIdx.x * 128, m0 = blockIdx.y * 128;
    if (n0 > m0) return;   // fully masked tile: never written, never read
    float* Cf = g_s + (size_t)bh * SS * SS;
    size_t ob = (size_t)bh * SS * DK;
    gemm_mma<0, true>(g_qh + ob, g_ql + ob, 512, g_kh + ob, g_kl + ob, 512,
                      512, m0, n0, 0.04419417382415922f, Cf, SS, nullptr, nullptr, 0);
}

// Softmax over valid (causal) prefix only.
__global__ void __launch_bounds__(256) k_softmax(void)
{
    int row  = blockIdx.x * 8 + (threadIdx.x >> 5);
    int lane = threadIdx.x & 31;
    int r    = row & (SS - 1);
    int rt   = r >> 7;             // last valid 128-col block
    const float4* p = reinterpret_cast<const float4*>(g_s + (size_t)row * SS);
    uint2* ph = reinterpret_cast<uint2*>(g_ph + (size_t)row * SS);
    uint2* pl = reinterpret_cast<uint2*>(g_pl + (size_t)row * SS);

    float4 v[16];
    float mx = -CUDART_INF_F;
#pragma unroll
    for (int i = 0; i < 16; i++) {
        if (i <= rt) {
            v[i] = p[lane + i * 32];
            mx = fmaxf(mx, fmaxf(fmaxf(v[i].x, v[i].y), fmaxf(v[i].z, v[i].w)));
        }
    }
#pragma unroll
    for (int o = 16; o; o >>= 1) mx = fmaxf(mx, __shfl_xor_sync(0xffffffffu, mx, o));
    float sum = 0.0f;
#pragma unroll
    for (int i = 0; i < 16; i++) {
        if (i > rt) continue;
        v[i].x = __expf(v[i].x - mx); v[i].y = __expf(v[i].y - mx);
        v[i].z = __expf(v[i].z - mx); v[i].w = __expf(v[i].w - mx);
        sum += (v[i].x + v[i].y) + (v[i].z + v[i].w);
    }
#pragma unroll
    for (int o = 16; o; o >>= 1) sum += __shfl_xor_sync(0xffffffffu, sum, o);
    float inv = 1.0f / sum;
#pragma unroll
    for (int i = 0; i < 16; i++) {
        if (i > rt) continue;
        float a0 = v[i].x*inv, a1 = v[i].y*inv, a2 = v[i].z*inv, a3 = v[i].w*inv;
        __nv_bfloat16 h0=__float2bfloat16(a0), h1=__float2bfloat16(a1),
                      h2=__float2bfloat16(a2), h3=__float2bfloat16(a3);
        __nv_bfloat16 l0=__float2bfloat16(a0-__bfloat162float(h0)),
                      l1=__float2bfloat16(a1-__bfloat162float(h1)),
                      l2=__float2bfloat16(a2-__bfloat162float(h2)),
                      l3=__float2bfloat16(a3-__bfloat162float(h3));
        ph[lane + i*32] = make_uint2(
            (uint32_t)__bfloat16_as_ushort(h0)|((uint32_t)__bfloat16_as_ushort(h1)<<16),
            (uint32_t)__bfloat16_as_ushort(h2)|((uint32_t)__bfloat16_as_ushort(h3)<<16));
        pl[lane + i*32] = make_uint2(
            (uint32_t)__bfloat16_as_ushort(l0)|((uint32_t)__bfloat16_as_ushort(l1)<<16),
            (uint32_t)__bfloat16_as_ushort(l2)|((uint32_t)__bfloat16_as_ushort(l3)<<16));
    }
}

// PV: NN gemm — A = probs [s][t], B = V natural [t][dk]
__global__ void __launch_bounds__(256, 2) k_pv_mma(void)
{
    int bh = blockIdx.z, b = bh >> 3, h = bh & 7;
    int m0 = blockIdx.y * 128, n0 = blockIdx.x * 128;
    const __nv_bfloat16* Ah = g_ph + (size_t)bh * SS * SS;
    const __nv_bfloat16* Al = g_pl + (size_t)bh * SS * SS;
    const __nv_bfloat16* Bh = g_vh + (size_t)bh * SS * DK;
    const __nv_bfloat16* Bl = g_vl + (size_t)bh * SS * DK;
    size_t base = (size_t)b * SS * 4096 + h * 512 + n0;
    gemm_mma<2, false>(Ah, Al, SS, Bh, Bl, 512, m0 + 128, m0, n0, 1.f,
                       nullptr, 0, g_hoh + base, g_hol + base, 4096);
}

__global__ void __launch_bounds__(256, 2) k_out_mma(float* __restrict__ out)
{
    int m0 = blockIdx.y * 128, n0 = blockIdx.x * 128;
    gemm_mma<1, true>(g_hoh, g_hol, 4096, g_wuh, g_wul, 4096, 4096, m0, n0, 1.f,
                      out, 512, nullptr, nullptr, 0);
}

// ---------------------------------------------------------------------------
extern "C" void kernel_launch(void* const* d_in, const int* in_sizes, int n_in,
                              void* d_out, int out_size)
{
    const float* x  = (const float*)d_in[0];
    const float* Wq = (const float*)d_in[1];
    const float* Wk = (const float*)d_in[2];
    const float* Wv = (const float*)d_in[3];
    const float* Wu = (const float*)d_in[4];
    float* out = (float*)d_out;

    cudaFuncSetAttribute(k_qkv_mma,    cudaFuncAttributeMaxDynamicSharedMemorySize, SMEM_DYN);
    cudaFuncSetAttribute(k_scores_mma, cudaFuncAttributeMaxDynamicSharedMemorySize, SMEM_DYN);
    cudaFuncSetAttribute(k_pv_mma,     cudaFuncAttributeMaxDynamicSharedMemorySize, SMEM_DYN);
    cudaFuncSetAttribute(k_out_mma,    cudaFuncAttributeMaxDynamicSharedMemorySize, SMEM_DYN);

    const int n4 = TT * DK / 4;           // 524288 float4s per 4096x512 array
    k_split_all <<<dim3(n4 / 256, 5), 256>>>(x, Wq, Wk, Wv, Wu);

    k_qkv_mma   <<<dim3(32, 32, 3),  256, SMEM_DYN>>>();
    k_scores_mma<<<dim3(16, 16, NH), 256, SMEM_DYN>>>();
    k_softmax   <<<NH * SS / 8, 256>>>();
    k_pv_mma    <<<dim3(4, 16, NH),  256, SMEM_DYN>>>();
    k_out_mma   <<<dim3(4, 32, 1),   256, SMEM_DYN>>>(out);
}